// round 13
// baseline (speedup 1.0000x reference)
#include <cuda_runtime.h>
#include <cuda_bf16.h>
#include <cstdint>

// Problem constants
#define BATCH   16
#define CDIM    512
#define LIN     1024
#define KW      3
#define LP      1022      // LIN - KW + 1
#define LPAD    1024      // padded scratch row stride (16B-aligned rows)
#define HEADS   8
#define DH      64        // CDIM / HEADS
#define SCALE   0.04419417382415922f   // 1/sqrt(512)

#define QKV_ELEMS (BATCH * CDIM * LPAD)
__device__ float g_q[QKV_ELEMS];   // tf32-rounded (q*SCALE)
__device__ float g_k[QKV_ELEMS];   // tf32-rounded k
__device__ float g_v[QKV_ELEMS];   // tf32-rounded v

// tf32-rounded copy of x (+pad for tail overread)
__device__ uint32_t g_xt[BATCH * CDIM * LIN + 16];
// packed tf32 weights: [cid][otile(4)][chunk(32)][tap*16+ch (48)][o (128)]
#define WPACK_CHUNK 6144                   // 48*128
#define WPACK_PER_CID (4 * 32 * WPACK_CHUNK)
__device__ uint32_t g_wt[3 * WPACK_PER_CID];

// ---------------------------------------------------------------------------
// tf32 / cp.async helpers
// ---------------------------------------------------------------------------
__device__ __forceinline__ uint32_t f2tf32(float f) {
    uint32_t r;
    asm("cvt.rna.tf32.f32 %0, %1;" : "=r"(r) : "f"(f));
    return r;
}

__device__ __forceinline__ void mma_tf32(float c[4], const uint32_t a[4],
                                         uint32_t b0, uint32_t b1) {
    asm volatile(
        "mma.sync.aligned.m16n8k8.row.col.f32.tf32.tf32.f32 "
        "{%0,%1,%2,%3},{%4,%5,%6,%7},{%8,%9},{%0,%1,%2,%3};"
        : "+f"(c[0]), "+f"(c[1]), "+f"(c[2]), "+f"(c[3])
        : "r"(a[0]), "r"(a[1]), "r"(a[2]), "r"(a[3]), "r"(b0), "r"(b1));
}

__device__ __forceinline__ void cp_async16(uint32_t smem_addr, const void* gptr) {
    asm volatile("cp.async.cg.shared.global [%0], [%1], 16;"
                 :: "r"(smem_addr), "l"(gptr));
}
#define CP_COMMIT()      asm volatile("cp.async.commit_group;")
#define CP_WAIT(n)       asm volatile("cp.async.wait_group %0;" :: "n"(n))

// ---------------------------------------------------------------------------
// Prep 1: round x to tf32 (bit-identical to the old per-load conversion).
// ---------------------------------------------------------------------------
__global__ __launch_bounds__(256)
void round_x_kernel(const float* __restrict__ x)
{
    const int i = blockIdx.x * 256 + threadIdx.x;   // float4 index
    const float4 v = ((const float4*)x)[i];
    uint4 u;
    u.x = f2tf32(v.x); u.y = f2tf32(v.y);
    u.z = f2tf32(v.z); u.w = f2tf32(v.w);
    ((uint4*)g_xt)[i] = u;
}

// ---------------------------------------------------------------------------
// Prep 2: pack weights into per-chunk smem-ready layout (tf32).
//   dst idx = (((cid*4+ot)*32+ck)*48 + (tap*16+ch))*128 + o
//   src     = w_cid[(ot*128+o)*1536 + (ck*16+ch)*3 + tap]
// ---------------------------------------------------------------------------
__global__ __launch_bounds__(256)
void pack_w_kernel(const float* __restrict__ w0,
                   const float* __restrict__ w1,
                   const float* __restrict__ w2)
{
    const int idx = blockIdx.x * 256 + threadIdx.x;  // 0 .. 3*WPACK_PER_CID-1
    const int o   = idx & 127;
    const int t1  = idx >> 7;
    const int r   = t1 % 48;
    const int t2  = t1 / 48;
    const int ck  = t2 & 31;
    const int t3  = t2 >> 5;
    const int ot  = t3 & 3;
    const int cid = t3 >> 2;
    const int tap = r >> 4;
    const int ch  = r & 15;
    const float* w = (cid == 0) ? w0 : (cid == 1) ? w1 : w2;
    const float v = w[(size_t)(ot * 128 + o) * (CDIM * KW) + (ck * 16 + ch) * KW + tap];
    g_wt[idx] = f2tf32(v);
}

// ---------------------------------------------------------------------------
// Conv1d, tf32 tensor cores, v6: 3-stage cp.async pipeline, ONE barrier
// per chunk. Block tile 128(o) x 128(l); 8 warps (4m x 2n), warp 32 x 64.
// Chunk = 16 channels (32 chunks). Buffers: 3 x 8704 u32 = 104 KB/CTA,
// 2 CTAs/SM. Chunk ck lives in buffer ck % 3; fill for ck+2 is issued at
// the TOP of iteration ck (its buffer was consumed at ck-1, proven by the
// single barrier). Strides 136 == 8 (mod 32): conflict-free fragment LDS.
// Grid: (8 l-tiles, 4 o-tiles, 48 = batch*3), 256 threads.
// ---------------------------------------------------------------------------
#define C_SS 136
#define CV_BUF 8704          // u32 per (W+X) buffer; X at offset 6528
#define CONV_SMEM_BYTES (3 * CV_BUF * 4)

__global__ __launch_bounds__(256, 2)
void conv_tf32_kernel(const float* __restrict__ bb0,
                      const float* __restrict__ bb1,
                      const float* __restrict__ bb2,
                      float* __restrict__ oq, float* __restrict__ ok,
                      float* __restrict__ ov)
{
    extern __shared__ uint32_t smu[];

    const int cid = blockIdx.z % 3;
    const int b   = blockIdx.z / 3;
    const float* bias = (cid == 0) ? bb0 : (cid == 1) ? bb1 : bb2;
    float*       out  = (cid == 0) ? oq  : (cid == 1) ? ok  : ov;
    const float  osc  = (cid == 0) ? SCALE : 1.f;

    const int ltile = blockIdx.x * 128;
    const int ot    = blockIdx.y;
    const int otile = ot * 128;

    const int tid  = threadIdx.x;
    const int lane = tid & 31;
    const int warp = tid >> 5;
    const int wm   = warp & 3;
    const int wn   = warp >> 2;
    const int g    = lane >> 2;
    const int tg   = lane & 3;

    const uint32_t* wtile = g_wt + (size_t)((cid * 4 + ot) * 32) * WPACK_CHUNK;
    const uint32_t* xbt   = g_xt + (size_t)b * CDIM * LIN;
    const uint32_t  sbase = (uint32_t)__cvta_generic_to_shared(smu);

    // ---- fill issue for one chunk into buffer `buf` ----
    auto issue_chunk = [&](int ck, int buf) {
        const uint32_t wdst = sbase + (buf * CV_BUF) * 4;
        const uint32_t xdst = wdst + 6528 * 4;
        const uint32_t* wsrc = wtile + (size_t)ck * WPACK_CHUNK;
        // W: 48 rows x 32 16B-segments = 1536 units
        #pragma unroll
        for (int j = 0; j < 6; j++) {
            const int unit = tid + 256 * j;
            const int r = unit >> 5, s = unit & 31;
            cp_async16(wdst + (r * C_SS + s * 4) * 4, wsrc + r * 128 + s * 4);
        }
        // X: 16 rows x 33 segments (cols 0..131) = 528 units
        #pragma unroll
        for (int j = 0; j < 3; j++) {
            const int unit = tid + 256 * j;
            if (unit < 528) {
                const int r = unit / 33, s = unit % 33;
                cp_async16(xdst + (r * C_SS + s * 4) * 4,
                           xbt + (size_t)(ck * 16 + r) * LIN + ltile + s * 4);
            }
        }
        CP_COMMIT();
    };

    float c[2][8][4];
    #pragma unroll
    for (int mi = 0; mi < 2; mi++)
        #pragma unroll
        for (int ni = 0; ni < 8; ni++)
            #pragma unroll
            for (int r = 0; r < 4; r++) c[mi][ni][r] = 0.f;

    // ---- prologue: chunks 0 and 1 into buffers 0 and 1 ----
    issue_chunk(0, 0);
    issue_chunk(1, 1);

    for (int ck = 0; ck < 32; ck++) {
        // wait for chunk ck's fill (<=1 newer group may remain in flight)
        if (ck < 31) CP_WAIT(1); else CP_WAIT(0);
        __syncthreads();   // fill visible to all; all warps past chunk ck-1

        // issue fill for ck+2 into buffer (ck+2)%3 (consumed at ck-1)
        if (ck + 2 < 32) issue_chunk(ck + 2, (ck + 2) % 3);

        const uint32_t* wsb = smu + (ck % 3) * CV_BUF;
        const uint32_t* xsb = wsb + 6528;

        #pragma unroll
        for (int tap = 0; tap < 3; tap++) {
            #pragma unroll
            for (int ks = 0; ks < 2; ks++) {
                const uint32_t* wsa = &wsb[(tap * 16 + ks * 8) * C_SS];
                const uint32_t* xsa = &xsb[(ks * 8) * C_SS];
                uint32_t a[2][4];
                #pragma unroll
                for (int mi = 0; mi < 2; mi++) {
                    const int row = wm * 32 + mi * 16;
                    a[mi][0] = wsa[(tg    ) * C_SS + row + g];
                    a[mi][1] = wsa[(tg    ) * C_SS + row + g + 8];
                    a[mi][2] = wsa[(tg + 4) * C_SS + row + g];
                    a[mi][3] = wsa[(tg + 4) * C_SS + row + g + 8];
                }
                #pragma unroll
                for (int ni = 0; ni < 8; ni++) {
                    const int coln = wn * 64 + ni * 8 + g + tap;
                    const uint32_t b0 = xsa[(tg    ) * C_SS + coln];
                    const uint32_t b1 = xsa[(tg + 4) * C_SS + coln];
                    mma_tf32(c[0][ni], a[0], b0, b1);
                    mma_tf32(c[1][ni], a[1], b0, b1);
                }
            }
        }
        // no bottom barrier: next iteration's top barrier covers reuse
    }

    // ---- epilogue: bias (+scale for q) + tf32 pre-round + store ----
    #pragma unroll
    for (int mi = 0; mi < 2; mi++) {
        const int r0 = otile + wm * 32 + mi * 16 + g;
        const int r1 = r0 + 8;
        const float bv0 = bias[r0];
        const float bv1 = bias[r1];
        float* row0 = out + ((size_t)b * CDIM + r0) * LPAD;
        float* row1 = out + ((size_t)b * CDIM + r1) * LPAD;
        #pragma unroll
        for (int ni = 0; ni < 8; ni++) {
            const int l0 = ltile + wn * 64 + ni * 8 + tg * 2;
            if (l0 < LP) {
                *(float2*)&row0[l0] = make_float2(
                    __uint_as_float(f2tf32((c[mi][ni][0] + bv0) * osc)),
                    __uint_as_float(f2tf32((c[mi][ni][1] + bv0) * osc)));
                *(float2*)&row1[l0] = make_float2(
                    __uint_as_float(f2tf32((c[mi][ni][2] + bv1) * osc)),
                    __uint_as_float(f2tf32((c[mi][ni][3] + bv1) * osc)));
            } else {
                *(float2*)&row0[l0] = make_float2(0.f, 0.f);
                *(float2*)&row1[l0] = make_float2(0.f, 0.f);
            }
        }
    }
}

// ---------------------------------------------------------------------------
// tf32 tensor-core flash attention (unchanged from R10).
// ---------------------------------------------------------------------------
#define ATTN_SMEM_U32  (8704 + 2 * (4608 + 4352))
#define ATTN_SMEM_BYTES (ATTN_SMEM_U32 * 4)
#define KV_STRIDE 8960          // u32 per K+V buffer

__global__ __launch_bounds__(256, 2)
void flash_attn_tf32_kernel(const float* __restrict__ gq,
                            const float* __restrict__ gk,
                            const float* __restrict__ gv,
                            float* __restrict__ out)
{
    extern __shared__ uint32_t smu[];
    uint32_t* Ps = smu;                        // P (stride 68), Ops alias

    const int qbase = blockIdx.x * 128;
    const int bh    = blockIdx.y;
    const int b     = bh >> 3;
    const int h     = bh & 7;
    const int tid   = threadIdx.x;
    const int lane  = tid & 31;
    const int w     = tid >> 5;
    const int g     = lane >> 2;
    const int tg    = lane & 3;
    const int qr    = w * 16;

    const size_t chan0 = ((size_t)b * CDIM + h * DH) * LPAD;
    const float* qg = gq + chan0;
    const float* kg = gk + chan0;
    const float* vg = gv + chan0;

    const uint32_t sbase = (uint32_t)__cvta_generic_to_shared(smu);
    const int d0 = tid >> 4;
    const int s4 = (tid & 15) * 4;

    #pragma unroll
    for (int bufsel = 0; bufsel < 2; bufsel++) {
        const uint32_t kb = sbase + (8704 + bufsel * KV_STRIDE) * 4;
        const uint32_t vb = kb + 4608 * 4;
        const int kbase = bufsel * 64;
        #pragma unroll
        for (int j = 0; j < 4; j++) {
            const int d = d0 + 16 * j;
            cp_async16(kb + (d * 72 + s4) * 4, kg + (size_t)d * LPAD + kbase + s4);
            cp_async16(vb + (d * 68 + s4) * 4, vg + (size_t)d * LPAD + kbase + s4);
        }
        CP_COMMIT();
    }

    const uint32_t* qgu = (const uint32_t*)qg;
    uint32_t aQ[8][4];
    #pragma unroll
    for (int ks = 0; ks < 8; ks++) {
        const size_t r0 = (size_t)(8 * ks + tg) * LPAD + qbase + qr + g;
        const size_t r1 = (size_t)(8 * ks + tg + 4) * LPAD + qbase + qr + g;
        aQ[ks][0] = qgu[r0];
        aQ[ks][1] = qgu[r0 + 8];
        aQ[ks][2] = qgu[r1];
        aQ[ks][3] = qgu[r1 + 8];
    }

    float m0 = -1e30f, m1 = -1e30f, l0 = 0.f, l1 = 0.f;
    float o[8][4];
    #pragma unroll
    for (int ni = 0; ni < 8; ni++)
        #pragma unroll
        for (int r = 0; r < 4; r++) o[ni][r] = 0.f;

    for (int kt = 0; kt < 16; kt++) {
        const int kbase = kt * 64;
        const int cur   = kt & 1;

        if (kt < 15) CP_WAIT(1); else CP_WAIT(0);
        __syncthreads();

        const uint32_t* Ks = smu + 8704 + cur * KV_STRIDE;
        const uint32_t* Vs = Ks + 4608;

        float c[8][4];
        #pragma unroll
        for (int ni = 0; ni < 8; ni++)
            #pragma unroll
            for (int r = 0; r < 4; r++) c[ni][r] = 0.f;

        #pragma unroll
        for (int ks = 0; ks < 8; ks++) {
            #pragma unroll
            for (int ni = 0; ni < 8; ni++) {
                const uint32_t b0 = Ks[(8 * ks + tg)     * 72 + 8 * ni + g];
                const uint32_t b1 = Ks[(8 * ks + tg + 4) * 72 + 8 * ni + g];
                mma_tf32(c[ni], aQ[ks], b0, b1);
            }
        }

        if (kt == 15) {
            #pragma unroll
            for (int ni = 0; ni < 8; ni++) {
                const int col = ni * 8 + 2 * tg;
                if (kbase + col     >= LP) { c[ni][0] = -1e30f; c[ni][2] = -1e30f; }
                if (kbase + col + 1 >= LP) { c[ni][1] = -1e30f; c[ni][3] = -1e30f; }
            }
        }

        float mx0 = -1e30f, mx1 = -1e30f;
        #pragma unroll
        for (int ni = 0; ni < 8; ni++) {
            mx0 = fmaxf(mx0, fmaxf(c[ni][0], c[ni][1]));
            mx1 = fmaxf(mx1, fmaxf(c[ni][2], c[ni][3]));
        }
        mx0 = fmaxf(mx0, __shfl_xor_sync(0xffffffffu, mx0, 1));
        mx0 = fmaxf(mx0, __shfl_xor_sync(0xffffffffu, mx0, 2));
        mx1 = fmaxf(mx1, __shfl_xor_sync(0xffffffffu, mx1, 1));
        mx1 = fmaxf(mx1, __shfl_xor_sync(0xffffffffu, mx1, 2));

        const float mn0 = fmaxf(m0, mx0);
        const float mn1 = fmaxf(m1, mx1);
        const float al0 = __expf(m0 - mn0);
        const float al1 = __expf(m1 - mn1);
        m0 = mn0; m1 = mn1;

        float s0 = 0.f, s1 = 0.f;
        #pragma unroll
        for (int ni = 0; ni < 8; ni++) {
            c[ni][0] = __expf(c[ni][0] - mn0);
            c[ni][1] = __expf(c[ni][1] - mn0);
            c[ni][2] = __expf(c[ni][2] - mn1);
            c[ni][3] = __expf(c[ni][3] - mn1);
            s0 += c[ni][0] + c[ni][1];
            s1 += c[ni][2] + c[ni][3];
        }
        s0 += __shfl_xor_sync(0xffffffffu, s0, 1);
        s0 += __shfl_xor_sync(0xffffffffu, s0, 2);
        s1 += __shfl_xor_sync(0xffffffffu, s1, 1);
        s1 += __shfl_xor_sync(0xffffffffu, s1, 2);
        l0 = l0 * al0 + s0;
        l1 = l1 * al1 + s1;

        #pragma unroll
        for (int ni = 0; ni < 8; ni++) {
            o[ni][0] *= al0; o[ni][1] *= al0;
            o[ni][2] *= al1; o[ni][3] *= al1;
        }

        #pragma unroll
        for (int ni = 0; ni < 8; ni++) {
            const int col = ni * 8 + 2 * tg;
            uint2 p0 = make_uint2(f2tf32(c[ni][0]), f2tf32(c[ni][1]));
            uint2 p1 = make_uint2(f2tf32(c[ni][2]), f2tf32(c[ni][3]));
            *(uint2*)&Ps[(qr + g)     * 68 + col] = p0;
            *(uint2*)&Ps[(qr + g + 8) * 68 + col] = p1;
        }
        __syncwarp();

        #pragma unroll
        for (int ks = 0; ks < 8; ks++) {
            uint32_t aP[4];
            aP[0] = Ps[(qr + g)     * 68 + 8 * ks + tg];
            aP[1] = Ps[(qr + g + 8) * 68 + 8 * ks + tg];
            aP[2] = Ps[(qr + g)     * 68 + 8 * ks + tg + 4];
            aP[3] = Ps[(qr + g + 8) * 68 + 8 * ks + tg + 4];
            #pragma unroll
            for (int ni = 0; ni < 8; ni++) {
                const uint32_t b0 = Vs[(8 * ni + g) * 68 + 8 * ks + tg];
                const uint32_t b1 = Vs[(8 * ni + g) * 68 + 8 * ks + tg + 4];
                mma_tf32(o[ni], aP, b0, b1);
            }
        }

        __syncthreads();
        if (kt + 2 < 16) {
            const uint32_t kb = sbase + (8704 + cur * KV_STRIDE) * 4;
            const uint32_t vb = kb + 4608 * 4;
            const int kb2 = (kt + 2) * 64;
            #pragma unroll
            for (int j = 0; j < 4; j++) {
                const int d = d0 + 16 * j;
                cp_async16(kb + (d * 72 + s4) * 4, kg + (size_t)d * LPAD + kb2 + s4);
                cp_async16(vb + (d * 68 + s4) * 4, vg + (size_t)d * LPAD + kb2 + s4);
            }
            CP_COMMIT();
        }
    }

    const float il0 = 1.f / l0;
    const float il1 = 1.f / l1;
    float* Ops = (float*)Ps;        // [d=64][q=128] stride 132
    #pragma unroll
    for (int ni = 0; ni < 8; ni++) {
        const int dd = ni * 8 + 2 * tg;
        Ops[dd * 132 + qr + g]           = o[ni][0] * il0;
        Ops[(dd + 1) * 132 + qr + g]     = o[ni][1] * il0;
        Ops[dd * 132 + qr + g + 8]       = o[ni][2] * il1;
        Ops[(dd + 1) * 132 + qr + g + 8] = o[ni][3] * il1;
    }
    __syncthreads();

    for (int t = tid; t < 64 * 128; t += 256) {
        const int d = t >> 7, q2 = t & 127;
        const int lq = qbase + q2;
        if (lq < LP)
            out[((size_t)b * CDIM + h * DH + d) * LP + lq] = Ops[d * 132 + q2];
    }
}

// ---------------------------------------------------------------------------
extern "C" void kernel_launch(void* const* d_in, const int* in_sizes, int n_in,
                              void* d_out, int out_size)
{
    const float* x  = (const float*)d_in[0];
    const float* w0 = (const float*)d_in[1];
    const float* b0 = (const float*)d_in[2];
    const float* w1 = (const float*)d_in[3];
    const float* b1 = (const float*)d_in[4];
    const float* w2 = (const float*)d_in[5];
    const float* b2 = (const float*)d_in[6];
    float* out = (float*)d_out;

    float *pq, *pk, *pv;
    cudaGetSymbolAddress((void**)&pq, g_q);
    cudaGetSymbolAddress((void**)&pk, g_k);
    cudaGetSymbolAddress((void**)&pv, g_v);

    // prep passes
    round_x_kernel<<<(BATCH * CDIM * LIN / 4) / 256, 256>>>(x);
    pack_w_kernel<<<(3 * WPACK_PER_CID) / 256, 256>>>(w0, w1, w2);

    cudaFuncSetAttribute(conv_tf32_kernel,
                         cudaFuncAttributeMaxDynamicSharedMemorySize,
                         CONV_SMEM_BYTES);
    dim3 cgrid(8, 4, BATCH * 3);
    conv_tf32_kernel<<<cgrid, 256, CONV_SMEM_BYTES>>>(b0, b1, b2, pq, pk, pv);

    cudaFuncSetAttribute(flash_attn_tf32_kernel,
                         cudaFuncAttributeMaxDynamicSharedMemorySize,
                         ATTN_SMEM_BYTES);
    dim3 agrid(8, 128);
    flash_attn_tf32_kernel<<<agrid, 256, ATTN_SMEM_BYTES>>>(pq, pk, pv, out);
}

// round 15
// speedup vs baseline: 1.0314x; 1.0314x over previous
#include <cuda_runtime.h>
#include <cuda_bf16.h>
#include <cstdint>

// Problem constants
#define BATCH   16
#define CDIM    512
#define LIN     1024
#define KW      3
#define LP      1022      // LIN - KW + 1
#define LPAD    1024      // padded scratch row stride (16B-aligned rows)
#define HEADS   8
#define DH      64        // CDIM / HEADS
#define SCALE   0.04419417382415922f   // 1/sqrt(512)

#define QKV_ELEMS (BATCH * CDIM * LPAD)
__device__ float g_q[QKV_ELEMS];   // tf32-rounded (q*SCALE)
__device__ float g_k[QKV_ELEMS];   // tf32-rounded k, KEY-PERMUTED within 8-groups
__device__ float g_v[QKV_ELEMS];   // tf32-rounded v (natural order)

// tf32-rounded copy of x (+pad for tail overread)
__device__ uint32_t g_xt[BATCH * CDIM * LIN + 16];
// packed tf32 weights: [cid][otile(4)][chunk(32)][tap*16+ch (48)][o (128)]
#define WPACK_CHUNK 6144                   // 48*128
#define WPACK_PER_CID (4 * 32 * WPACK_CHUNK)
__device__ uint32_t g_wt[3 * WPACK_PER_CID];

// ---------------------------------------------------------------------------
// tf32 / cp.async helpers
// ---------------------------------------------------------------------------
__device__ __forceinline__ uint32_t f2tf32(float f) {
    uint32_t r;
    asm("cvt.rna.tf32.f32 %0, %1;" : "=r"(r) : "f"(f));
    return r;
}

__device__ __forceinline__ void mma_tf32(float c[4], const uint32_t a[4],
                                         uint32_t b0, uint32_t b1) {
    asm volatile(
        "mma.sync.aligned.m16n8k8.row.col.f32.tf32.tf32.f32 "
        "{%0,%1,%2,%3},{%4,%5,%6,%7},{%8,%9},{%0,%1,%2,%3};"
        : "+f"(c[0]), "+f"(c[1]), "+f"(c[2]), "+f"(c[3])
        : "r"(a[0]), "r"(a[1]), "r"(a[2]), "r"(a[3]), "r"(b0), "r"(b1));
}

__device__ __forceinline__ void cp_async16(uint32_t smem_addr, const void* gptr) {
    asm volatile("cp.async.cg.shared.global [%0], [%1], 16;"
                 :: "r"(smem_addr), "l"(gptr));
}
#define CP_COMMIT()      asm volatile("cp.async.commit_group;")
#define CP_WAIT(n)       asm volatile("cp.async.wait_group %0;" :: "n"(n))

// key-permutation: key l is stored at column (l&~7)|pi_inv(l&7),
// pi_inv = [0,2,4,6,1,3,5,7]  (so stored position p holds key pi(p),
// pi = [0,4,1,5,2,6,3,7]; pi(2t)=t, pi(2t+1)=t+4)
__device__ __forceinline__ int kperm(int l) {
    return (l & ~7) | (((l & 3) << 1) | ((l >> 2) & 1));
}

// ---------------------------------------------------------------------------
// Prep 1: round x to tf32 (bit-identical to the old per-load conversion).
// ---------------------------------------------------------------------------
__global__ __launch_bounds__(256)
void round_x_kernel(const float* __restrict__ x)
{
    const int i = blockIdx.x * 256 + threadIdx.x;   // float4 index
    const float4 v = ((const float4*)x)[i];
    uint4 u;
    u.x = f2tf32(v.x); u.y = f2tf32(v.y);
    u.z = f2tf32(v.z); u.w = f2tf32(v.w);
    ((uint4*)g_xt)[i] = u;
}

// ---------------------------------------------------------------------------
// Prep 2: pack weights into per-chunk smem-ready layout (tf32).
// ---------------------------------------------------------------------------
__global__ __launch_bounds__(256)
void pack_w_kernel(const float* __restrict__ w0,
                   const float* __restrict__ w1,
                   const float* __restrict__ w2)
{
    const int idx = blockIdx.x * 256 + threadIdx.x;  // 0 .. 3*WPACK_PER_CID-1
    const int o   = idx & 127;
    const int t1  = idx >> 7;
    const int r   = t1 % 48;
    const int t2  = t1 / 48;
    const int ck  = t2 & 31;
    const int t3  = t2 >> 5;
    const int ot  = t3 & 3;
    const int cid = t3 >> 2;
    const int tap = r >> 4;
    const int ch  = r & 15;
    const float* w = (cid == 0) ? w0 : (cid == 1) ? w1 : w2;
    const float v = w[(size_t)(ot * 128 + o) * (CDIM * KW) + (ck * 16 + ch) * KW + tap];
    g_wt[idx] = f2tf32(v);
}

// ---------------------------------------------------------------------------
// Conv1d, tf32 tensor cores, v6 (3-stage cp.async pipeline, one barrier
// per chunk) — epilogue stores k with permuted key columns.
// ---------------------------------------------------------------------------
#define C_SS 136
#define CV_BUF 8704          // u32 per (W+X) buffer; X at offset 6528
#define CONV_SMEM_BYTES (3 * CV_BUF * 4)

__global__ __launch_bounds__(256, 2)
void conv_tf32_kernel(const float* __restrict__ bb0,
                      const float* __restrict__ bb1,
                      const float* __restrict__ bb2,
                      float* __restrict__ oq, float* __restrict__ ok,
                      float* __restrict__ ov)
{
    extern __shared__ uint32_t smu[];

    const int cid = blockIdx.z % 3;
    const int b   = blockIdx.z / 3;
    const float* bias = (cid == 0) ? bb0 : (cid == 1) ? bb1 : bb2;
    float*       out  = (cid == 0) ? oq  : (cid == 1) ? ok  : ov;
    const float  osc  = (cid == 0) ? SCALE : 1.f;

    const int ltile = blockIdx.x * 128;
    const int ot    = blockIdx.y;
    const int otile = ot * 128;

    const int tid  = threadIdx.x;
    const int lane = tid & 31;
    const int warp = tid >> 5;
    const int wm   = warp & 3;
    const int wn   = warp >> 2;
    const int g    = lane >> 2;
    const int tg   = lane & 3;

    const uint32_t* wtile = g_wt + (size_t)((cid * 4 + ot) * 32) * WPACK_CHUNK;
    const uint32_t* xbt   = g_xt + (size_t)b * CDIM * LIN;
    const uint32_t  sbase = (uint32_t)__cvta_generic_to_shared(smu);

    auto issue_chunk = [&](int ck, int buf) {
        const uint32_t wdst = sbase + (buf * CV_BUF) * 4;
        const uint32_t xdst = wdst + 6528 * 4;
        const uint32_t* wsrc = wtile + (size_t)ck * WPACK_CHUNK;
        #pragma unroll
        for (int j = 0; j < 6; j++) {
            const int unit = tid + 256 * j;
            const int r = unit >> 5, s = unit & 31;
            cp_async16(wdst + (r * C_SS + s * 4) * 4, wsrc + r * 128 + s * 4);
        }
        #pragma unroll
        for (int j = 0; j < 3; j++) {
            const int unit = tid + 256 * j;
            if (unit < 528) {
                const int r = unit / 33, s = unit % 33;
                cp_async16(xdst + (r * C_SS + s * 4) * 4,
                           xbt + (size_t)(ck * 16 + r) * LIN + ltile + s * 4);
            }
        }
        CP_COMMIT();
    };

    float c[2][8][4];
    #pragma unroll
    for (int mi = 0; mi < 2; mi++)
        #pragma unroll
        for (int ni = 0; ni < 8; ni++)
            #pragma unroll
            for (int r = 0; r < 4; r++) c[mi][ni][r] = 0.f;

    issue_chunk(0, 0);
    issue_chunk(1, 1);

    for (int ck = 0; ck < 32; ck++) {
        if (ck < 31) CP_WAIT(1); else CP_WAIT(0);
        __syncthreads();

        if (ck + 2 < 32) issue_chunk(ck + 2, (ck + 2) % 3);

        const uint32_t* wsb = smu + (ck % 3) * CV_BUF;
        const uint32_t* xsb = wsb + 6528;

        #pragma unroll
        for (int tap = 0; tap < 3; tap++) {
            #pragma unroll
            for (int ks = 0; ks < 2; ks++) {
                const uint32_t* wsa = &wsb[(tap * 16 + ks * 8) * C_SS];
                const uint32_t* xsa = &xsb[(ks * 8) * C_SS];
                uint32_t a[2][4];
                #pragma unroll
                for (int mi = 0; mi < 2; mi++) {
                    const int row = wm * 32 + mi * 16;
                    a[mi][0] = wsa[(tg    ) * C_SS + row + g];
                    a[mi][1] = wsa[(tg    ) * C_SS + row + g + 8];
                    a[mi][2] = wsa[(tg + 4) * C_SS + row + g];
                    a[mi][3] = wsa[(tg + 4) * C_SS + row + g + 8];
                }
                #pragma unroll
                for (int ni = 0; ni < 8; ni++) {
                    const int coln = wn * 64 + ni * 8 + g + tap;
                    const uint32_t b0 = xsa[(tg    ) * C_SS + coln];
                    const uint32_t b1 = xsa[(tg + 4) * C_SS + coln];
                    mma_tf32(c[0][ni], a[0], b0, b1);
                    mma_tf32(c[1][ni], a[1], b0, b1);
                }
            }
        }
    }

    // ---- epilogue: bias (+scale for q) + tf32 pre-round + store ----
    #pragma unroll
    for (int mi = 0; mi < 2; mi++) {
        const int r0 = otile + wm * 32 + mi * 16 + g;
        const int r1 = r0 + 8;
        const float bv0 = bias[r0];
        const float bv1 = bias[r1];
        float* row0 = out + ((size_t)b * CDIM + r0) * LPAD;
        float* row1 = out + ((size_t)b * CDIM + r1) * LPAD;
        #pragma unroll
        for (int ni = 0; ni < 8; ni++) {
            const int l0 = ltile + wn * 64 + ni * 8 + tg * 2;
            if (cid == 1) {
                // k: permuted key columns (scalar stores)
                #pragma unroll
                for (int e = 0; e < 2; e++) {
                    const int l  = l0 + e;
                    const int lp = kperm(l);
                    row0[lp] = (l < LP)
                        ? __uint_as_float(f2tf32(c[mi][ni][e]     + bv0)) : 0.f;
                    row1[lp] = (l < LP)
                        ? __uint_as_float(f2tf32(c[mi][ni][2 + e] + bv1)) : 0.f;
                }
            } else if (l0 < LP) {
                *(float2*)&row0[l0] = make_float2(
                    __uint_as_float(f2tf32((c[mi][ni][0] + bv0) * osc)),
                    __uint_as_float(f2tf32((c[mi][ni][1] + bv0) * osc)));
                *(float2*)&row1[l0] = make_float2(
                    __uint_as_float(f2tf32((c[mi][ni][2] + bv1) * osc)),
                    __uint_as_float(f2tf32((c[mi][ni][3] + bv1) * osc)));
            } else {
                *(float2*)&row0[l0] = make_float2(0.f, 0.f);
                *(float2*)&row1[l0] = make_float2(0.f, 0.f);
            }
        }
    }
}

// ---------------------------------------------------------------------------
// tf32 tensor-core flash attention, v3: K key-permuted so the S-mma output
// registers ARE the PV A-fragment (P never touches smem).
// Smem (u32): Ops scratch [8704] (epilogue only),
//             2 x { Ks[4608] stride 72, Vs[4352] stride 68 }.
// Grid: (8 q-tiles, 128 bh), 256 threads, 2 CTAs/SM.
// ---------------------------------------------------------------------------
#define ATTN_SMEM_U32  (8704 + 2 * (4608 + 4352))
#define ATTN_SMEM_BYTES (ATTN_SMEM_U32 * 4)
#define KV_STRIDE 8960          // u32 per K+V buffer

__global__ __launch_bounds__(256, 2)
void flash_attn_tf32_kernel(const float* __restrict__ gq,
                            const float* __restrict__ gk,
                            const float* __restrict__ gv,
                            float* __restrict__ out)
{
    extern __shared__ uint32_t smu[];

    const int qbase = blockIdx.x * 128;
    const int bh    = blockIdx.y;
    const int b     = bh >> 3;
    const int h     = bh & 7;
    const int tid   = threadIdx.x;
    const int lane  = tid & 31;
    const int w     = tid >> 5;
    const int g     = lane >> 2;
    const int tg    = lane & 3;
    const int qr    = w * 16;

    const size_t chan0 = ((size_t)b * CDIM + h * DH) * LPAD;
    const float* qg = gq + chan0;
    const float* kg = gk + chan0;
    const float* vg = gv + chan0;

    const uint32_t sbase = (uint32_t)__cvta_generic_to_shared(smu);
    const int d0 = tid >> 4;
    const int s4 = (tid & 15) * 4;

    #pragma unroll
    for (int bufsel = 0; bufsel < 2; bufsel++) {
        const uint32_t kb = sbase + (8704 + bufsel * KV_STRIDE) * 4;
        const uint32_t vb = kb + 4608 * 4;
        const int kbase = bufsel * 64;
        #pragma unroll
        for (int j = 0; j < 4; j++) {
            const int d = d0 + 16 * j;
            cp_async16(kb + (d * 72 + s4) * 4, kg + (size_t)d * LPAD + kbase + s4);
            cp_async16(vb + (d * 68 + s4) * 4, vg + (size_t)d * LPAD + kbase + s4);
        }
        CP_COMMIT();
    }

    const uint32_t* qgu = (const uint32_t*)qg;
    uint32_t aQ[8][4];
    #pragma unroll
    for (int ks = 0; ks < 8; ks++) {
        const size_t r0 = (size_t)(8 * ks + tg) * LPAD + qbase + qr + g;
        const size_t r1 = (size_t)(8 * ks + tg + 4) * LPAD + qbase + qr + g;
        aQ[ks][0] = qgu[r0];
        aQ[ks][1] = qgu[r0 + 8];
        aQ[ks][2] = qgu[r1];
        aQ[ks][3] = qgu[r1 + 8];
    }

    float m0 = -1e30f, m1 = -1e30f, l0 = 0.f, l1 = 0.f;
    float o[8][4];
    #pragma unroll
    for (int ni = 0; ni < 8; ni++)
        #pragma unroll
        for (int r = 0; r < 4; r++) o[ni][r] = 0.f;

    for (int kt = 0; kt < 16; kt++) {
        const int kbase = kt * 64;
        const int cur   = kt & 1;

        if (kt < 15) CP_WAIT(1); else CP_WAIT(0);
        __syncthreads();

        const uint32_t* Ks = smu + 8704 + cur * KV_STRIDE;
        const uint32_t* Vs = Ks + 4608;

        // ---- S = Q^T K  (K columns are permuted positions) ----
        float c[8][4];
        #pragma unroll
        for (int ni = 0; ni < 8; ni++)
            #pragma unroll
            for (int r = 0; r < 4; r++) c[ni][r] = 0.f;

        #pragma unroll
        for (int ks = 0; ks < 8; ks++) {
            #pragma unroll
            for (int ni = 0; ni < 8; ni++) {
                const uint32_t b0 = Ks[(8 * ks + tg)     * 72 + 8 * ni + g];
                const uint32_t b1 = Ks[(8 * ks + tg + 4) * 72 + 8 * ni + g];
                mma_tf32(c[ni], aQ[ks], b0, b1);
            }
        }

        // ---- mask by ACTUAL key index (pi(2tg)=tg, pi(2tg+1)=tg+4) ----
        if (kt == 15) {
            #pragma unroll
            for (int ni = 0; ni < 8; ni++) {
                const int key0 = kbase + 8 * ni + tg;
                if (key0     >= LP) { c[ni][0] = -1e30f; c[ni][2] = -1e30f; }
                if (key0 + 4 >= LP) { c[ni][1] = -1e30f; c[ni][3] = -1e30f; }
            }
        }

        // ---- online softmax (permutation-invariant) ----
        float mx0 = -1e30f, mx1 = -1e30f;
        #pragma unroll
        for (int ni = 0; ni < 8; ni++) {
            mx0 = fmaxf(mx0, fmaxf(c[ni][0], c[ni][1]));
            mx1 = fmaxf(mx1, fmaxf(c[ni][2], c[ni][3]));
        }
        mx0 = fmaxf(mx0, __shfl_xor_sync(0xffffffffu, mx0, 1));
        mx0 = fmaxf(mx0, __shfl_xor_sync(0xffffffffu, mx0, 2));
        mx1 = fmaxf(mx1, __shfl_xor_sync(0xffffffffu, mx1, 1));
        mx1 = fmaxf(mx1, __shfl_xor_sync(0xffffffffu, mx1, 2));

        const float mn0 = fmaxf(m0, mx0);
        const float mn1 = fmaxf(m1, mx1);
        const float al0 = __expf(m0 - mn0);
        const float al1 = __expf(m1 - mn1);
        m0 = mn0; m1 = mn1;

        float s0 = 0.f, s1 = 0.f;
        #pragma unroll
        for (int ni = 0; ni < 8; ni++) {
            c[ni][0] = __expf(c[ni][0] - mn0);
            c[ni][1] = __expf(c[ni][1] - mn0);
            c[ni][2] = __expf(c[ni][2] - mn1);
            c[ni][3] = __expf(c[ni][3] - mn1);
            s0 += c[ni][0] + c[ni][1];
            s1 += c[ni][2] + c[ni][3];
        }
        s0 += __shfl_xor_sync(0xffffffffu, s0, 1);
        s0 += __shfl_xor_sync(0xffffffffu, s0, 2);
        s1 += __shfl_xor_sync(0xffffffffu, s1, 1);
        s1 += __shfl_xor_sync(0xffffffffu, s1, 2);
        l0 = l0 * al0 + s0;
        l1 = l1 * al1 + s1;

        #pragma unroll
        for (int ni = 0; ni < 8; ni++) {
            o[ni][0] *= al0; o[ni][1] *= al0;
            o[ni][2] *= al1; o[ni][3] *= al1;
        }

        // ---- O += P V : P comes straight from c registers (renamed) ----
        #pragma unroll
        for (int ks = 0; ks < 8; ks++) {
            uint32_t aP[4];
            aP[0] = f2tf32(c[ks][0]);   // P[g   ][key tg  ]
            aP[1] = f2tf32(c[ks][2]);   // P[g+8 ][key tg  ]
            aP[2] = f2tf32(c[ks][1]);   // P[g   ][key tg+4]
            aP[3] = f2tf32(c[ks][3]);   // P[g+8 ][key tg+4]
            #pragma unroll
            for (int ni = 0; ni < 8; ni++) {
                const uint32_t b0 = Vs[(8 * ni + g) * 68 + 8 * ks + tg];
                const uint32_t b1 = Vs[(8 * ni + g) * 68 + 8 * ks + tg + 4];
                mma_tf32(o[ni], aP, b0, b1);
            }
        }

        __syncthreads();
        if (kt + 2 < 16) {
            const uint32_t kb = sbase + (8704 + cur * KV_STRIDE) * 4;
            const uint32_t vb = kb + 4608 * 4;
            const int kb2 = (kt + 2) * 64;
            #pragma unroll
            for (int j = 0; j < 4; j++) {
                const int d = d0 + 16 * j;
                cp_async16(kb + (d * 72 + s4) * 4, kg + (size_t)d * LPAD + kb2 + s4);
                cp_async16(vb + (d * 68 + s4) * 4, vg + (size_t)d * LPAD + kb2 + s4);
            }
            CP_COMMIT();
        }
    }

    // ---- epilogue: divide by l, transpose through smem, coalesced store ----
    const float il0 = 1.f / l0;
    const float il1 = 1.f / l1;
    float* Ops = (float*)smu;        // [d=64][q=128] stride 132
    #pragma unroll
    for (int ni = 0; ni < 8; ni++) {
        const int dd = ni * 8 + 2 * tg;
        Ops[dd * 132 + qr + g]           = o[ni][0] * il0;
        Ops[(dd + 1) * 132 + qr + g]     = o[ni][1] * il0;
        Ops[dd * 132 + qr + g + 8]       = o[ni][2] * il1;
        Ops[(dd + 1) * 132 + qr + g + 8] = o[ni][3] * il1;
    }
    __syncthreads();

    for (int t = tid; t < 64 * 128; t += 256) {
        const int d = t >> 7, q2 = t & 127;
        const int lq = qbase + q2;
        if (lq < LP)
            out[((size_t)b * CDIM + h * DH + d) * LP + lq] = Ops[d * 132 + q2];
    }
}

// ---------------------------------------------------------------------------
extern "C" void kernel_launch(void* const* d_in, const int* in_sizes, int n_in,
                              void* d_out, int out_size)
{
    const float* x  = (const float*)d_in[0];
    const float* w0 = (const float*)d_in[1];
    const float* b0 = (const float*)d_in[2];
    const float* w1 = (const float*)d_in[3];
    const float* b1 = (const float*)d_in[4];
    const float* w2 = (const float*)d_in[5];
    const float* b2 = (const float*)d_in[6];
    float* out = (float*)d_out;

    float *pq, *pk, *pv;
    cudaGetSymbolAddress((void**)&pq, g_q);
    cudaGetSymbolAddress((void**)&pk, g_k);
    cudaGetSymbolAddress((void**)&pv, g_v);

    // prep passes
    round_x_kernel<<<(BATCH * CDIM * LIN / 4) / 256, 256>>>(x);
    pack_w_kernel<<<(3 * WPACK_PER_CID) / 256, 256>>>(w0, w1, w2);

    cudaFuncSetAttribute(conv_tf32_kernel,
                         cudaFuncAttributeMaxDynamicSharedMemorySize,
                         CONV_SMEM_BYTES);
    dim3 cgrid(8, 4, BATCH * 3);
    conv_tf32_kernel<<<cgrid, 256, CONV_SMEM_BYTES>>>(b0, b1, b2, pq, pk, pv);

    cudaFuncSetAttribute(flash_attn_tf32_kernel,
                         cudaFuncAttributeMaxDynamicSharedMemorySize,
                         ATTN_SMEM_BYTES);
    dim3 agrid(8, 128);
    flash_attn_tf32_kernel<<<agrid, 256, ATTN_SMEM_BYTES>>>(pq, pk, pv, out);
}

// round 16
// speedup vs baseline: 1.0829x; 1.0499x over previous
#include <cuda_runtime.h>
#include <cuda_bf16.h>
#include <cstdint>

// Problem constants
#define BATCH   16
#define CDIM    512
#define LIN     1024
#define KW      3
#define LP      1022      // LIN - KW + 1
#define LPAD    1024      // padded scratch row stride (16B-aligned rows)
#define HEADS   8
#define DH      64        // CDIM / HEADS
#define SCALE   0.04419417382415922f   // 1/sqrt(512)

#define QKV_ELEMS (BATCH * CDIM * LPAD)
__device__ float g_q[QKV_ELEMS];   // tf32-rounded (q*SCALE)
__device__ float g_k[QKV_ELEMS];   // tf32-rounded k, KEY-PERMUTED within 8-groups
__device__ float g_v[QKV_ELEMS];   // tf32-rounded v (natural order)

// tf32-rounded copy of x (+pad for tail overread)
__device__ uint32_t g_xt[BATCH * CDIM * LIN + 16];
// packed tf32 weights, A-FRAGMENT layout:
//   [cid][otile(4)][chunk(32)][tap*2+ks (6)][wm(4)][mi(2)][lane(32)][4]
#define WPACK_CHUNK 6144                   // 6*4*2*32*4
#define WPACK_PER_CID (4 * 32 * WPACK_CHUNK)
__device__ uint32_t g_wt[3 * WPACK_PER_CID];

// ---------------------------------------------------------------------------
// tf32 / cp.async helpers
// ---------------------------------------------------------------------------
__device__ __forceinline__ uint32_t f2tf32(float f) {
    uint32_t r;
    asm("cvt.rna.tf32.f32 %0, %1;" : "=r"(r) : "f"(f));
    return r;
}

__device__ __forceinline__ void mma_tf32(float c[4], const uint32_t a[4],
                                         uint32_t b0, uint32_t b1) {
    asm volatile(
        "mma.sync.aligned.m16n8k8.row.col.f32.tf32.tf32.f32 "
        "{%0,%1,%2,%3},{%4,%5,%6,%7},{%8,%9},{%0,%1,%2,%3};"
        : "+f"(c[0]), "+f"(c[1]), "+f"(c[2]), "+f"(c[3])
        : "r"(a[0]), "r"(a[1]), "r"(a[2]), "r"(a[3]), "r"(b0), "r"(b1));
}

__device__ __forceinline__ void cp_async16(uint32_t smem_addr, const void* gptr) {
    asm volatile("cp.async.cg.shared.global [%0], [%1], 16;"
                 :: "r"(smem_addr), "l"(gptr));
}
#define CP_COMMIT()      asm volatile("cp.async.commit_group;")
#define CP_WAIT(n)       asm volatile("cp.async.wait_group %0;" :: "n"(n))

// key-permutation: key l is stored at column (l&~7)|pi_inv(l&7)
__device__ __forceinline__ int kperm(int l) {
    return (l & ~7) | (((l & 3) << 1) | ((l >> 2) & 1));
}

// ---------------------------------------------------------------------------
// Prep 1: round x to tf32.
// ---------------------------------------------------------------------------
__global__ __launch_bounds__(256)
void round_x_kernel(const float* __restrict__ x)
{
    const int i = blockIdx.x * 256 + threadIdx.x;   // float4 index
    const float4 v = ((const float4*)x)[i];
    uint4 u;
    u.x = f2tf32(v.x); u.y = f2tf32(v.y);
    u.z = f2tf32(v.z); u.w = f2tf32(v.w);
    ((uint4*)g_xt)[i] = u;
}

// ---------------------------------------------------------------------------
// Prep 2: pack weights into A-FRAGMENT layout (tf32).
// Per chunk, fragment f = tap*2+ks (ks = 8-channel half), warp row block wm,
// mi: each lane stores its 4 mma A-operands contiguously:
//   e0: W[o0][c0]  e1: W[o0+8][c0]  e2: W[o0][c0+4]  e3: W[o0+8][c0+4]
// with o0 = wm*32+mi*16+g, c0 = ck*16+ks*8+tg (g=lane>>2, tg=lane&3).
// ---------------------------------------------------------------------------
__global__ __launch_bounds__(256)
void pack_w_kernel(const float* __restrict__ w0,
                   const float* __restrict__ w1,
                   const float* __restrict__ w2)
{
    const int idx = blockIdx.x * 256 + threadIdx.x;  // 0 .. 3*WPACK_PER_CID-1
    const int local = idx % WPACK_CHUNK;
    const int rest  = idx / WPACK_CHUNK;
    const int ck  = rest & 31;
    const int ot  = (rest >> 5) & 3;
    const int cid = rest >> 7;

    const int e    = local & 3;
    const int lane = (local >> 2) & 31;
    const int mi   = (local >> 7) & 1;
    const int wm   = (local >> 8) & 3;
    const int ksl  = (local >> 10) & 1;
    const int tap  = local >> 11;            // 0..2
    const int g    = lane >> 2;
    const int tg   = lane & 3;

    const int o = wm * 32 + mi * 16 + g + (e & 1) * 8;
    const int c = ck * 16 + ksl * 8 + tg + (e >> 1) * 4;

    const float* w = (cid == 0) ? w0 : (cid == 1) ? w1 : w2;
    const float v = w[(size_t)(ot * 128 + o) * (CDIM * KW) + c * KW + tap];
    g_wt[idx] = f2tf32(v);
}

// ---------------------------------------------------------------------------
// Conv1d, tf32 tensor cores, v7: 3-stage cp.async pipeline + fragment-packed
// W (A loads are single LDS.128 per (tap,ks,mi): 12 vector LDS instead of
// 48 scalar per warp/chunk). W buffer is linear (6144 u32); X strided C_SS.
// Grid: (8 l-tiles, 4 o-tiles, 48 = batch*3), 256 threads, 2 CTAs/SM.
// ---------------------------------------------------------------------------
#define C_SS 136
#define CV_BUF 8320          // u32 per buffer: W 6144 + X 16*136=2176
#define CONV_SMEM_BYTES (3 * CV_BUF * 4)

__global__ __launch_bounds__(256, 2)
void conv_tf32_kernel(const float* __restrict__ bb0,
                      const float* __restrict__ bb1,
                      const float* __restrict__ bb2,
                      float* __restrict__ oq, float* __restrict__ ok,
                      float* __restrict__ ov)
{
    extern __shared__ uint32_t smu[];

    const int cid = blockIdx.z % 3;
    const int b   = blockIdx.z / 3;
    const float* bias = (cid == 0) ? bb0 : (cid == 1) ? bb1 : bb2;
    float*       out  = (cid == 0) ? oq  : (cid == 1) ? ok  : ov;
    const float  osc  = (cid == 0) ? SCALE : 1.f;

    const int ltile = blockIdx.x * 128;
    const int ot    = blockIdx.y;
    const int otile = ot * 128;

    const int tid  = threadIdx.x;
    const int lane = tid & 31;
    const int warp = tid >> 5;
    const int wm   = warp & 3;
    const int wn   = warp >> 2;
    const int g    = lane >> 2;
    const int tg   = lane & 3;

    const uint32_t* wtile = g_wt + (size_t)((cid * 4 + ot) * 32) * WPACK_CHUNK;
    const uint32_t* xbt   = g_xt + (size_t)b * CDIM * LIN;
    const uint32_t  sbase = (uint32_t)__cvta_generic_to_shared(smu);

    auto issue_chunk = [&](int ck, int buf) {
        const uint32_t wdst = sbase + (buf * CV_BUF) * 4;
        const uint32_t xdst = wdst + 6144 * 4;
        const uint32_t* wsrc = wtile + (size_t)ck * WPACK_CHUNK;
        // W: linear 1536 16B units (both sides contiguous)
        #pragma unroll
        for (int j = 0; j < 6; j++) {
            const int unit = tid + 256 * j;
            cp_async16(wdst + unit * 16, wsrc + unit * 4);
        }
        // X: 16 rows x 33 segments (cols 0..131) = 528 units
        #pragma unroll
        for (int j = 0; j < 3; j++) {
            const int unit = tid + 256 * j;
            if (unit < 528) {
                const int r = unit / 33, s = unit % 33;
                cp_async16(xdst + (r * C_SS + s * 4) * 4,
                           xbt + (size_t)(ck * 16 + r) * LIN + ltile + s * 4);
            }
        }
        CP_COMMIT();
    };

    float c[2][8][4];
    #pragma unroll
    for (int mi = 0; mi < 2; mi++)
        #pragma unroll
        for (int ni = 0; ni < 8; ni++)
            #pragma unroll
            for (int r = 0; r < 4; r++) c[mi][ni][r] = 0.f;

    issue_chunk(0, 0);
    issue_chunk(1, 1);

    for (int ck = 0; ck < 32; ck++) {
        if (ck < 31) CP_WAIT(1); else CP_WAIT(0);
        __syncthreads();

        if (ck + 2 < 32) issue_chunk(ck + 2, (ck + 2) % 3);

        const uint32_t* wsb = smu + (ck % 3) * CV_BUF;
        const uint32_t* xsb = wsb + 6144;

        #pragma unroll
        for (int tap = 0; tap < 3; tap++) {
            #pragma unroll
            for (int ks = 0; ks < 2; ks++) {
                // A fragments: one LDS.128 per mi
                const uint32_t* afrag =
                    wsb + (((tap * 2 + ks) * 4 + wm) * 2) * 128 + lane * 4;
                uint32_t a[2][4];
                #pragma unroll
                for (int mi = 0; mi < 2; mi++) {
                    const uint4 av = *(const uint4*)(afrag + mi * 128);
                    a[mi][0] = av.x; a[mi][1] = av.y;
                    a[mi][2] = av.z; a[mi][3] = av.w;
                }
                const uint32_t* xsa = &xsb[(ks * 8) * C_SS];
                #pragma unroll
                for (int ni = 0; ni < 8; ni++) {
                    const int coln = wn * 64 + ni * 8 + g + tap;
                    const uint32_t b0 = xsa[(tg    ) * C_SS + coln];
                    const uint32_t b1 = xsa[(tg + 4) * C_SS + coln];
                    mma_tf32(c[0][ni], a[0], b0, b1);
                    mma_tf32(c[1][ni], a[1], b0, b1);
                }
            }
        }
    }

    // ---- epilogue: bias (+scale for q) + tf32 pre-round + store ----
    #pragma unroll
    for (int mi = 0; mi < 2; mi++) {
        const int r0 = otile + wm * 32 + mi * 16 + g;
        const int r1 = r0 + 8;
        const float bv0 = bias[r0];
        const float bv1 = bias[r1];
        float* row0 = out + ((size_t)b * CDIM + r0) * LPAD;
        float* row1 = out + ((size_t)b * CDIM + r1) * LPAD;
        #pragma unroll
        for (int ni = 0; ni < 8; ni++) {
            const int l0 = ltile + wn * 64 + ni * 8 + tg * 2;
            if (cid == 1) {
                // k: permuted key columns (scalar stores)
                #pragma unroll
                for (int e = 0; e < 2; e++) {
                    const int l  = l0 + e;
                    const int lp = kperm(l);
                    row0[lp] = (l < LP)
                        ? __uint_as_float(f2tf32(c[mi][ni][e]     + bv0)) : 0.f;
                    row1[lp] = (l < LP)
                        ? __uint_as_float(f2tf32(c[mi][ni][2 + e] + bv1)) : 0.f;
                }
            } else if (l0 < LP) {
                *(float2*)&row0[l0] = make_float2(
                    __uint_as_float(f2tf32((c[mi][ni][0] + bv0) * osc)),
                    __uint_as_float(f2tf32((c[mi][ni][1] + bv0) * osc)));
                *(float2*)&row1[l0] = make_float2(
                    __uint_as_float(f2tf32((c[mi][ni][2] + bv1) * osc)),
                    __uint_as_float(f2tf32((c[mi][ni][3] + bv1) * osc)));
            } else {
                *(float2*)&row0[l0] = make_float2(0.f, 0.f);
                *(float2*)&row1[l0] = make_float2(0.f, 0.f);
            }
        }
    }
}

// ---------------------------------------------------------------------------
// tf32 tensor-core flash attention, v3 (unchanged from R15): K key-permuted
// so S-mma output registers ARE the PV A-fragment (P never touches smem).
// ---------------------------------------------------------------------------
#define ATTN_SMEM_U32  (8704 + 2 * (4608 + 4352))
#define ATTN_SMEM_BYTES (ATTN_SMEM_U32 * 4)
#define KV_STRIDE 8960          // u32 per K+V buffer

__global__ __launch_bounds__(256, 2)
void flash_attn_tf32_kernel(const float* __restrict__ gq,
                            const float* __restrict__ gk,
                            const float* __restrict__ gv,
                            float* __restrict__ out)
{
    extern __shared__ uint32_t smu[];

    const int qbase = blockIdx.x * 128;
    const int bh    = blockIdx.y;
    const int b     = bh >> 3;
    const int h     = bh & 7;
    const int tid   = threadIdx.x;
    const int lane  = tid & 31;
    const int w     = tid >> 5;
    const int g     = lane >> 2;
    const int tg    = lane & 3;
    const int qr    = w * 16;

    const size_t chan0 = ((size_t)b * CDIM + h * DH) * LPAD;
    const float* qg = gq + chan0;
    const float* kg = gk + chan0;
    const float* vg = gv + chan0;

    const uint32_t sbase = (uint32_t)__cvta_generic_to_shared(smu);
    const int d0 = tid >> 4;
    const int s4 = (tid & 15) * 4;

    #pragma unroll
    for (int bufsel = 0; bufsel < 2; bufsel++) {
        const uint32_t kb = sbase + (8704 + bufsel * KV_STRIDE) * 4;
        const uint32_t vb = kb + 4608 * 4;
        const int kbase = bufsel * 64;
        #pragma unroll
        for (int j = 0; j < 4; j++) {
            const int d = d0 + 16 * j;
            cp_async16(kb + (d * 72 + s4) * 4, kg + (size_t)d * LPAD + kbase + s4);
            cp_async16(vb + (d * 68 + s4) * 4, vg + (size_t)d * LPAD + kbase + s4);
        }
        CP_COMMIT();
    }

    const uint32_t* qgu = (const uint32_t*)qg;
    uint32_t aQ[8][4];
    #pragma unroll
    for (int ks = 0; ks < 8; ks++) {
        const size_t r0 = (size_t)(8 * ks + tg) * LPAD + qbase + qr + g;
        const size_t r1 = (size_t)(8 * ks + tg + 4) * LPAD + qbase + qr + g;
        aQ[ks][0] = qgu[r0];
        aQ[ks][1] = qgu[r0 + 8];
        aQ[ks][2] = qgu[r1];
        aQ[ks][3] = qgu[r1 + 8];
    }

    float m0 = -1e30f, m1 = -1e30f, l0 = 0.f, l1 = 0.f;
    float o[8][4];
    #pragma unroll
    for (int ni = 0; ni < 8; ni++)
        #pragma unroll
        for (int r = 0; r < 4; r++) o[ni][r] = 0.f;

    for (int kt = 0; kt < 16; kt++) {
        const int kbase = kt * 64;
        const int cur   = kt & 1;

        if (kt < 15) CP_WAIT(1); else CP_WAIT(0);
        __syncthreads();

        const uint32_t* Ks = smu + 8704 + cur * KV_STRIDE;
        const uint32_t* Vs = Ks + 4608;

        // ---- S = Q^T K  (K columns are permuted positions) ----
        float c[8][4];
        #pragma unroll
        for (int ni = 0; ni < 8; ni++)
            #pragma unroll
            for (int r = 0; r < 4; r++) c[ni][r] = 0.f;

        #pragma unroll
        for (int ks = 0; ks < 8; ks++) {
            #pragma unroll
            for (int ni = 0; ni < 8; ni++) {
                const uint32_t b0 = Ks[(8 * ks + tg)     * 72 + 8 * ni + g];
                const uint32_t b1 = Ks[(8 * ks + tg + 4) * 72 + 8 * ni + g];
                mma_tf32(c[ni], aQ[ks], b0, b1);
            }
        }

        // ---- mask by ACTUAL key index (pi(2tg)=tg, pi(2tg+1)=tg+4) ----
        if (kt == 15) {
            #pragma unroll
            for (int ni = 0; ni < 8; ni++) {
                const int key0 = kbase + 8 * ni + tg;
                if (key0     >= LP) { c[ni][0] = -1e30f; c[ni][2] = -1e30f; }
                if (key0 + 4 >= LP) { c[ni][1] = -1e30f; c[ni][3] = -1e30f; }
            }
        }

        // ---- online softmax (permutation-invariant) ----
        float mx0 = -1e30f, mx1 = -1e30f;
        #pragma unroll
        for (int ni = 0; ni < 8; ni++) {
            mx0 = fmaxf(mx0, fmaxf(c[ni][0], c[ni][1]));
            mx1 = fmaxf(mx1, fmaxf(c[ni][2], c[ni][3]));
        }
        mx0 = fmaxf(mx0, __shfl_xor_sync(0xffffffffu, mx0, 1));
        mx0 = fmaxf(mx0, __shfl_xor_sync(0xffffffffu, mx0, 2));
        mx1 = fmaxf(mx1, __shfl_xor_sync(0xffffffffu, mx1, 1));
        mx1 = fmaxf(mx1, __shfl_xor_sync(0xffffffffu, mx1, 2));

        const float mn0 = fmaxf(m0, mx0);
        const float mn1 = fmaxf(m1, mx1);
        const float al0 = __expf(m0 - mn0);
        const float al1 = __expf(m1 - mn1);
        m0 = mn0; m1 = mn1;

        float s0 = 0.f, s1 = 0.f;
        #pragma unroll
        for (int ni = 0; ni < 8; ni++) {
            c[ni][0] = __expf(c[ni][0] - mn0);
            c[ni][1] = __expf(c[ni][1] - mn0);
            c[ni][2] = __expf(c[ni][2] - mn1);
            c[ni][3] = __expf(c[ni][3] - mn1);
            s0 += c[ni][0] + c[ni][1];
            s1 += c[ni][2] + c[ni][3];
        }
        s0 += __shfl_xor_sync(0xffffffffu, s0, 1);
        s0 += __shfl_xor_sync(0xffffffffu, s0, 2);
        s1 += __shfl_xor_sync(0xffffffffu, s1, 1);
        s1 += __shfl_xor_sync(0xffffffffu, s1, 2);
        l0 = l0 * al0 + s0;
        l1 = l1 * al1 + s1;

        #pragma unroll
        for (int ni = 0; ni < 8; ni++) {
            o[ni][0] *= al0; o[ni][1] *= al0;
            o[ni][2] *= al1; o[ni][3] *= al1;
        }

        // ---- O += P V : P comes straight from c registers (renamed) ----
        #pragma unroll
        for (int ks = 0; ks < 8; ks++) {
            uint32_t aP[4];
            aP[0] = f2tf32(c[ks][0]);   // P[g   ][key tg  ]
            aP[1] = f2tf32(c[ks][2]);   // P[g+8 ][key tg  ]
            aP[2] = f2tf32(c[ks][1]);   // P[g   ][key tg+4]
            aP[3] = f2tf32(c[ks][3]);   // P[g+8 ][key tg+4]
            #pragma unroll
            for (int ni = 0; ni < 8; ni++) {
                const uint32_t b0 = Vs[(8 * ni + g) * 68 + 8 * ks + tg];
                const uint32_t b1 = Vs[(8 * ni + g) * 68 + 8 * ks + tg + 4];
                mma_tf32(o[ni], aP, b0, b1);
            }
        }

        __syncthreads();
        if (kt + 2 < 16) {
            const uint32_t kb = sbase + (8704 + cur * KV_STRIDE) * 4;
            const uint32_t vb = kb + 4608 * 4;
            const int kb2 = (kt + 2) * 64;
            #pragma unroll
            for (int j = 0; j < 4; j++) {
                const int d = d0 + 16 * j;
                cp_async16(kb + (d * 72 + s4) * 4, kg + (size_t)d * LPAD + kb2 + s4);
                cp_async16(vb + (d * 68 + s4) * 4, vg + (size_t)d * LPAD + kb2 + s4);
            }
            CP_COMMIT();
        }
    }

    // ---- epilogue: divide by l, transpose through smem, coalesced store ----
    const float il0 = 1.f / l0;
    const float il1 = 1.f / l1;
    float* Ops = (float*)smu;        // [d=64][q=128] stride 132
    #pragma unroll
    for (int ni = 0; ni < 8; ni++) {
        const int dd = ni * 8 + 2 * tg;
        Ops[dd * 132 + qr + g]           = o[ni][0] * il0;
        Ops[(dd + 1) * 132 + qr + g]     = o[ni][1] * il0;
        Ops[dd * 132 + qr + g + 8]       = o[ni][2] * il1;
        Ops[(dd + 1) * 132 + qr + g + 8] = o[ni][3] * il1;
    }
    __syncthreads();

    for (int t = tid; t < 64 * 128; t += 256) {
        const int d = t >> 7, q2 = t & 127;
        const int lq = qbase + q2;
        if (lq < LP)
            out[((size_t)b * CDIM + h * DH + d) * LP + lq] = Ops[d * 132 + q2];
    }
}

// ---------------------------------------------------------------------------
extern "C" void kernel_launch(void* const* d_in, const int* in_sizes, int n_in,
                              void* d_out, int out_size)
{
    const float* x  = (const float*)d_in[0];
    const float* w0 = (const float*)d_in[1];
    const float* b0 = (const float*)d_in[2];
    const float* w1 = (const float*)d_in[3];
    const float* b1 = (const float*)d_in[4];
    const float* w2 = (const float*)d_in[5];
    const float* b2 = (const float*)d_in[6];
    float* out = (float*)d_out;

    float *pq, *pk, *pv;
    cudaGetSymbolAddress((void**)&pq, g_q);
    cudaGetSymbolAddress((void**)&pk, g_k);
    cudaGetSymbolAddress((void**)&pv, g_v);

    // prep passes
    round_x_kernel<<<(BATCH * CDIM * LIN / 4) / 256, 256>>>(x);
    pack_w_kernel<<<(3 * WPACK_PER_CID) / 256, 256>>>(w0, w1, w2);

    cudaFuncSetAttribute(conv_tf32_kernel,
                         cudaFuncAttributeMaxDynamicSharedMemorySize,
                         CONV_SMEM_BYTES);
    dim3 cgrid(8, 4, BATCH * 3);
    conv_tf32_kernel<<<cgrid, 256, CONV_SMEM_BYTES>>>(b0, b1, b2, pq, pk, pv);

    cudaFuncSetAttribute(flash_attn_tf32_kernel,
                         cudaFuncAttributeMaxDynamicSharedMemorySize,
                         ATTN_SMEM_BYTES);
    dim3 agrid(8, 128);
    flash_attn_tf32_kernel<<<agrid, 256, ATTN_SMEM_BYTES>>>(pq, pk, pv, out);
}